// round 12
// baseline (speedup 1.0000x reference)
#include <cuda_runtime.h>
#include <cstdint>

#define MTOK 32768
#define DIN  1024
#define DH   512
#define DC   256
#define NC   128

__device__ float g_H[(size_t)MTOK * DH];
__device__ float g_E[(size_t)MTOK * DC];
__device__ float g_rowNorm[MTOK];
__device__ float g_sqerr[MTOK];
__device__ float g_cnorm[NC];

__device__ __forceinline__ uint32_t smem_u32(const void* p) {
    uint32_t a;
    asm("{ .reg .u64 t; cvta.to.shared.u64 t, %1; cvt.u32.u64 %0, t; }" : "=r"(a) : "l"(p));
    return a;
}
__device__ __forceinline__ void mma_tf32(float* d, const uint32_t* a, const uint32_t* b) {
    asm volatile(
        "mma.sync.aligned.m16n8k8.row.col.f32.tf32.tf32.f32 "
        "{%0,%1,%2,%3}, {%4,%5,%6,%7}, {%8,%9}, {%0,%1,%2,%3};"
        : "+f"(d[0]), "+f"(d[1]), "+f"(d[2]), "+f"(d[3])
        : "r"(a[0]), "r"(a[1]), "r"(a[2]), "r"(a[3]), "r"(b[0]), "r"(b[1]));
}
__device__ __forceinline__ void split_tf32(float v, uint32_t& hi, uint32_t& lo) {
    uint32_t h = __float_as_uint(v) & 0xFFFFE000u;
    float l = v - __uint_as_float(h);
    uint32_t lr;
    asm("cvt.rna.tf32.f32 %0, %1;" : "=r"(lr) : "f"(l));
    hi = h; lo = lr;
}

#define CPA16(dst, src) \
    asm volatile("cp.async.cg.shared.global [%0], [%1], 16;" :: "r"(dst), "l"(src) : "memory")
#define CPA_COMMIT() asm volatile("cp.async.commit_group;" ::: "memory")
#define CPA_WAIT2()  asm volatile("cp.async.wait_group 2;"  ::: "memory")

// ====== 3xTF32 mma.sync GEMM: 512 thr, BM=128 BN=256, warp tile 64x32 ========
// 16 warps (2 M x 8 N), 4-stage cp.async.
// stage: A [128][20] f (10240 B) then B [16][264] f (16896 B).
#define A_STR   20
#define B_STR   264
#define STG_FLT 6784
#define STG_B   27136
#define GEMM_SMEM (STG_B * 4)

template<bool RELU>
__global__ __launch_bounds__(512)
void gemm_mma(const float* __restrict__ A, const float* __restrict__ B,
              const float* __restrict__ bias, float* __restrict__ C,
              int N, int K)
{
    extern __shared__ float sm[];
    const uint32_t smb = smem_u32(sm);

    const int tid  = threadIdx.x;
    const int wid  = tid >> 5;
    const int lane = tid & 31;
    const int quad = lane & 3;
    const int qrow = lane >> 2;

    const int row0 = blockIdx.y * 128;
    const int col0 = blockIdx.x * 256;
    const int wm0  = (wid >> 3) * 64;      // 0 or 64
    const int wn0  = (wid & 7) * 32;       // 0..224

    // A: 512 float4 chunks, 1 per thread
    const int arow = tid >> 2;             // 0..127
    const int acol = (tid & 3) * 4;        // 0,4,8,12
    const float* Aptr = A + (size_t)(row0 + arow) * K + acol;
    const uint32_t aDst = smb + (uint32_t)(arow * A_STR + acol) * 4u;

    const int NK = K >> 4;

    auto issue = [&](int kt) {
        const uint32_t so = (uint32_t)(kt & 3) * (uint32_t)STG_B;
        CPA16(aDst + so, Aptr + kt * 16);
        #pragma unroll
        for (int j = 0; j < 2; ++j) {
            const int g  = tid + j * 512;    // 0..1023
            const int br = g >> 6;           // 0..15
            const int cc = g & 63;           // x4 floats
            const float* src = B + (size_t)(kt * 16 + br) * N + col0 + cc * 4;
            const uint32_t dst = smb + so + 10240u + (uint32_t)(br * B_STR + cc * 4) * 4u;
            CPA16(dst, src);
        }
    };

    issue(0); CPA_COMMIT();
    issue(1); CPA_COMMIT();
    issue(2); CPA_COMMIT();

    float acc[4][4][4] = {};

    for (int kt = 0; kt < NK; ++kt) {
        CPA_WAIT2();
        __syncthreads();
        if (kt + 3 < NK) issue(kt + 3);
        CPA_COMMIT();

        const float* Asm = sm + (kt & 3) * STG_FLT;
        const float* Bsm = Asm + 128 * A_STR;

        #pragma unroll
        for (int k8 = 0; k8 < 16; k8 += 8) {
            const float* Bk0 = Bsm + (k8 + quad) * B_STR;
            const float* Bk1 = Bsm + (k8 + quad + 4) * B_STR;
            uint32_t bh[4][2], bl[4][2];
            #pragma unroll
            for (int u = 0; u < 4; ++u) {
                const int nn = wn0 + 8 * u + qrow;
                split_tf32(Bk0[nn], bh[u][0], bl[u][0]);
                split_tf32(Bk1[nn], bh[u][1], bl[u][1]);
            }
            #pragma unroll
            for (int t = 0; t < 4; ++t) {
                const int mi = wm0 + 16 * t + qrow;
                const float* Am0 = Asm + mi * A_STR + k8 + quad;
                const float* Am1 = Asm + (mi + 8) * A_STR + k8 + quad;
                uint32_t ah[4], al[4];
                split_tf32(Am0[0], ah[0], al[0]);
                split_tf32(Am1[0], ah[1], al[1]);
                split_tf32(Am0[4], ah[2], al[2]);
                split_tf32(Am1[4], ah[3], al[3]);
                #pragma unroll
                for (int u = 0; u < 4; ++u) mma_tf32(acc[t][u], ah, bl[u]);
                #pragma unroll
                for (int u = 0; u < 4; ++u) mma_tf32(acc[t][u], al, bh[u]);
                #pragma unroll
                for (int u = 0; u < 4; ++u) mma_tf32(acc[t][u], ah, bh[u]);
            }
        }
    }

    #pragma unroll
    for (int u = 0; u < 4; ++u) {
        const int c = col0 + wn0 + 8 * u + 2 * quad;
        const float bj0 = bias[c], bj1 = bias[c + 1];
        #pragma unroll
        for (int t = 0; t < 4; ++t) {
            const int r0 = row0 + wm0 + 16 * t + qrow;
            float v00 = acc[t][u][0] + bj0;
            float v01 = acc[t][u][1] + bj1;
            float v10 = acc[t][u][2] + bj0;
            float v11 = acc[t][u][3] + bj1;
            if (RELU) {
                v00 = fmaxf(v00, 0.0f); v01 = fmaxf(v01, 0.0f);
                v10 = fmaxf(v10, 0.0f); v11 = fmaxf(v11, 0.0f);
            }
            *(float2*)(C + (size_t)r0 * N + c)       = make_float2(v00, v01);
            *(float2*)(C + (size_t)(r0 + 8) * N + c) = make_float2(v10, v11);
        }
    }
}

__global__ __launch_bounds__(256)
void rownorm_kernel()
{
    const int gtid = blockIdx.x * blockDim.x + threadIdx.x;
    const int row  = gtid >> 5;
    const int lane = gtid & 31;
    const float4* e = (const float4*)(g_E + (size_t)row * DC);
    float4 v1 = e[lane];
    float4 v2 = e[lane + 32];
    float s = v1.x * v1.x + v1.y * v1.y + v1.z * v1.z + v1.w * v1.w
            + v2.x * v2.x + v2.y * v2.y + v2.z * v2.z + v2.w * v2.w;
    #pragma unroll
    for (int off = 16; off > 0; off >>= 1)
        s += __shfl_xor_sync(0xffffffffu, s, off);
    if (lane == 0) g_rowNorm[row] = s;
}

__global__ void cnorm_kernel(const float* __restrict__ cb)
{
    const int n    = blockIdx.x;
    const int lane = threadIdx.x;
    const float4* c = (const float4*)(cb + (size_t)n * DC);
    float4 v1 = c[lane];
    float4 v2 = c[lane + 32];
    float s = v1.x * v1.x + v1.y * v1.y + v1.z * v1.z + v1.w * v1.w
            + v2.x * v2.x + v2.y * v2.y + v2.z * v2.z + v2.w * v2.w;
    #pragma unroll
    for (int off = 16; off > 0; off >>= 1)
        s += __shfl_xor_sync(0xffffffffu, s, off);
    if (lane == 0) g_cnorm[n] = s;
}

__global__ __launch_bounds__(256, 2)
void argmin_kernel(const float* __restrict__ cb, float* __restrict__ out)
{
    constexpr int BM = 128, BK = 8;
    __shared__ __align__(16) float As[2][BK][BM];
    __shared__ __align__(16) float Bs[2][BK][NC];
    __shared__ float cn[NC];

    const int tid = threadIdx.x;
    const int tx  = tid & 15;
    const int ty  = tid >> 4;
    const int row0 = blockIdx.x * BM;

    if (tid < NC) cn[tid] = g_cnorm[tid];

    const int arow = tid >> 1;
    const int acol = (tid & 1) * 4;
    const int bn   = tid >> 1;
    const int bk   = (tid & 1) * 4;

    const float* Aptr = g_E + (size_t)(row0 + arow) * DC + acol;
    const float* Bptr = cb  + (size_t)bn * DC + bk;

    float4 av = *(const float4*)Aptr;
    float4 bv = *(const float4*)Bptr;
    As[0][acol + 0][arow] = av.x;
    As[0][acol + 1][arow] = av.y;
    As[0][acol + 2][arow] = av.z;
    As[0][acol + 3][arow] = av.w;
    Bs[0][bk + 0][bn] = bv.x;
    Bs[0][bk + 1][bn] = bv.y;
    Bs[0][bk + 2][bn] = bv.z;
    Bs[0][bk + 3][bn] = bv.w;
    __syncthreads();

    float acc[8][8] = {};
    const int nk = DC / BK;
    int buf = 0;
    for (int kt = 0; kt < nk; ++kt) {
        float4 av2, bv2;
        const bool more = (kt + 1 < nk);
        if (more) {
            av2 = *(const float4*)(Aptr + (kt + 1) * BK);
            bv2 = *(const float4*)(Bptr + (kt + 1) * BK);
        }
        #pragma unroll
        for (int k = 0; k < BK; ++k) {
            float a[8], b[8];
            *(float4*)&a[0] = *(const float4*)&As[buf][k][ty * 8];
            *(float4*)&a[4] = *(const float4*)&As[buf][k][ty * 8 + 4];
            *(float4*)&b[0] = *(const float4*)&Bs[buf][k][tx * 8];
            *(float4*)&b[4] = *(const float4*)&Bs[buf][k][tx * 8 + 4];
            #pragma unroll
            for (int i = 0; i < 8; ++i)
                #pragma unroll
                for (int j = 0; j < 8; ++j)
                    acc[i][j] = fmaf(a[i], b[j], acc[i][j]);
        }
        if (more) {
            As[buf ^ 1][acol + 0][arow] = av2.x;
            As[buf ^ 1][acol + 1][arow] = av2.y;
            As[buf ^ 1][acol + 2][arow] = av2.z;
            As[buf ^ 1][acol + 3][arow] = av2.w;
            Bs[buf ^ 1][bk + 0][bn] = bv2.x;
            Bs[buf ^ 1][bk + 1][bn] = bv2.y;
            Bs[buf ^ 1][bk + 2][bn] = bv2.z;
            Bs[buf ^ 1][bk + 3][bn] = bv2.w;
            buf ^= 1;
            __syncthreads();
        }
    }

    #pragma unroll
    for (int i = 0; i < 8; ++i) {
        float mv = 3.0e38f;
        int   mi = 0;
        #pragma unroll
        for (int j = 0; j < 8; ++j) {
            float v = cn[tx * 8 + j] - 2.0f * acc[i][j];
            if (v < mv) { mv = v; mi = tx * 8 + j; }
        }
        #pragma unroll
        for (int off = 8; off >= 1; off >>= 1) {
            float ov = __shfl_xor_sync(0xffffffffu, mv, off);
            int   oi = __shfl_xor_sync(0xffffffffu, mi, off);
            if (ov < mv || (ov == mv && oi < mi)) { mv = ov; mi = oi; }
        }
        if (tx == 0) {
            const int r = row0 + ty * 8 + i;
            out[r]      = (float)mi;
            g_sqerr[r]  = g_rowNorm[r] + mv;
        }
    }
}

__global__ void reduce_loss_kernel(float* __restrict__ out)
{
    __shared__ double sm[1024];
    const int tid = threadIdx.x;
    double s = 0.0;
    for (int i = tid; i < MTOK; i += 1024) s += (double)g_sqerr[i];
    sm[tid] = s;
    __syncthreads();
    for (int off = 512; off > 0; off >>= 1) {
        if (tid < off) sm[tid] += sm[tid + off];
        __syncthreads();
    }
    if (tid == 0) {
        const float loss = (float)(sm[0] / ((double)MTOK * (double)DC));
        out[MTOK + 0] = loss;
        out[MTOK + 1] = loss;
        out[MTOK + 2] = 1.25f * loss;
    }
}

extern "C" void kernel_launch(void* const* d_in, const int* in_sizes, int n_in,
                              void* d_out, int out_size)
{
    const float* x  = (const float*)d_in[0];
    const float* W1 = (const float*)d_in[1];
    const float* b1 = (const float*)d_in[2];
    const float* W2 = (const float*)d_in[3];
    const float* b2 = (const float*)d_in[4];
    const float* cb = (const float*)d_in[5];
    float* out = (float*)d_out;

    float* H = (float*)0; float* E = (float*)0;
    cudaGetSymbolAddress((void**)&H, g_H);
    cudaGetSymbolAddress((void**)&E, g_E);

    cudaFuncSetAttribute(gemm_mma<true>,
                         cudaFuncAttributeMaxDynamicSharedMemorySize, GEMM_SMEM);
    cudaFuncSetAttribute(gemm_mma<false>,
                         cudaFuncAttributeMaxDynamicSharedMemorySize, GEMM_SMEM);

    gemm_mma<true ><<<dim3(DH / 256, MTOK / 128), 512, GEMM_SMEM>>>(x, W1, b1, H, DH, DIN);
    gemm_mma<false><<<dim3(DC / 256, MTOK / 128), 512, GEMM_SMEM>>>(H, W2, b2, E, DC, DH);
    rownorm_kernel<<<MTOK / 8, 256>>>();
    cnorm_kernel<<<NC, 32>>>(cb);
    argmin_kernel<<<MTOK / 128, 256>>>(cb, out);
    reduce_loss_kernel<<<1, 1024>>>(out);
}

// round 13
// speedup vs baseline: 1.1831x; 1.1831x over previous
#include <cuda_runtime.h>
#include <cstdint>

#define MTOK 32768
#define DIN  1024
#define DH   512
#define DC   256
#define NC   128

__device__ float g_H[(size_t)MTOK * DH];
__device__ float g_E[(size_t)MTOK * DC];
__device__ float g_rowNorm[MTOK];
__device__ float g_sqerr[MTOK];
__device__ float g_cnorm[NC];

__device__ __forceinline__ uint32_t smem_u32(const void* p) {
    uint32_t a;
    asm("{ .reg .u64 t; cvta.to.shared.u64 t, %1; cvt.u32.u64 %0, t; }" : "=r"(a) : "l"(p));
    return a;
}
__device__ __forceinline__ void mma_tf32(float* d, const uint32_t* a, const uint32_t* b) {
    asm volatile(
        "mma.sync.aligned.m16n8k8.row.col.f32.tf32.tf32.f32 "
        "{%0,%1,%2,%3}, {%4,%5,%6,%7}, {%8,%9}, {%0,%1,%2,%3};"
        : "+f"(d[0]), "+f"(d[1]), "+f"(d[2]), "+f"(d[3])
        : "r"(a[0]), "r"(a[1]), "r"(a[2]), "r"(a[3]), "r"(b[0]), "r"(b[1]));
}
__device__ __forceinline__ void split_tf32(float v, uint32_t& hi, uint32_t& lo) {
    uint32_t h = __float_as_uint(v) & 0xFFFFE000u;
    float l = v - __uint_as_float(h);
    uint32_t lr;
    asm("cvt.rna.tf32.f32 %0, %1;" : "=r"(lr) : "f"(l));
    hi = h; lo = lr;
}

#define CPA16(dst, src) \
    asm volatile("cp.async.cg.shared.global [%0], [%1], 16;" :: "r"(dst), "l"(src) : "memory")
#define CPA_COMMIT() asm volatile("cp.async.commit_group;" ::: "memory")
#define CPA_WAIT2()  asm volatile("cp.async.wait_group 2;"  ::: "memory")

// ===== 3xTF32 mma.sync GEMM, 4-stage cp.async, BM=128 BN=128, 2 CTAs/SM ======
// 256 threads, 8 warps (2x4), warp tile 64x32.
// stage: A [128][20] floats (10240 B) then B [16][136] floats (8704 B).
#define A_STR   20
#define B_STR   136
#define STG_FLT 4736
#define STG_B   18944
#define GEMM_SMEM (STG_B * 4)        // 75776 B -> two CTAs fit per SM

template<bool RELU>
__global__ __launch_bounds__(256, 2)
void gemm_mma(const float* __restrict__ A, const float* __restrict__ B,
              const float* __restrict__ bias, float* __restrict__ C,
              int N, int K)
{
    extern __shared__ float sm[];
    const uint32_t smb = smem_u32(sm);

    const int tid  = threadIdx.x;
    const int wid  = tid >> 5;
    const int lane = tid & 31;
    const int quad = lane & 3;
    const int qrow = lane >> 2;

    const int row0 = blockIdx.y * 128;
    const int col0 = blockIdx.x * 128;
    const int wm0  = (wid >> 2) * 64;
    const int wn0  = (wid & 3) * 32;

    const int arow = tid >> 1;               // 0..127
    const int acol = (tid & 1) * 8;          // 0 or 8
    const float* Aptr = A + (size_t)(row0 + arow) * K + acol;
    const int br0 = tid >> 5;                // 0..7
    const int bc0 = (tid & 31) * 4;          // 0..124
    const float* Bp0 = B + (size_t)br0 * N + col0 + bc0;
    const float* Bp1 = B + (size_t)(br0 + 8) * N + col0 + bc0;

    const uint32_t aDst  = smb + (uint32_t)(arow * A_STR + acol) * 4u;
    const uint32_t bDst0 = smb + 10240u + (uint32_t)(br0 * B_STR + bc0) * 4u;
    const uint32_t bDst1 = smb + 10240u + (uint32_t)((br0 + 8) * B_STR + bc0) * 4u;

    const int NK = K >> 4;

    auto issue = [&](int kt) {
        const uint32_t so = (uint32_t)(kt & 3) * (uint32_t)STG_B;
        const float* ap = Aptr + kt * 16;
        CPA16(aDst + so,        ap);
        CPA16(aDst + so + 16u,  ap + 4);
        const size_t bo = (size_t)kt * 16 * N;
        CPA16(bDst0 + so, Bp0 + bo);
        CPA16(bDst1 + so, Bp1 + bo);
    };

    issue(0); CPA_COMMIT();
    issue(1); CPA_COMMIT();
    issue(2); CPA_COMMIT();

    float acc[4][4][4] = {};

    for (int kt = 0; kt < NK; ++kt) {
        CPA_WAIT2();
        __syncthreads();
        if (kt + 3 < NK) issue(kt + 3);
        CPA_COMMIT();

        const float* Asm = sm + (kt & 3) * STG_FLT;
        const float* Bsm = Asm + 128 * A_STR;

        #pragma unroll
        for (int k8 = 0; k8 < 16; k8 += 8) {
            const float* Bk0 = Bsm + (k8 + quad) * B_STR;
            const float* Bk1 = Bsm + (k8 + quad + 4) * B_STR;
            uint32_t bh[4][2], bl[4][2];
            #pragma unroll
            for (int u = 0; u < 4; ++u) {
                const int nn = wn0 + 8 * u + qrow;
                split_tf32(Bk0[nn], bh[u][0], bl[u][0]);
                split_tf32(Bk1[nn], bh[u][1], bl[u][1]);
            }
            #pragma unroll
            for (int t = 0; t < 4; ++t) {
                const int mi = wm0 + 16 * t + qrow;
                const float* Am0 = Asm + mi * A_STR + k8 + quad;
                const float* Am1 = Asm + (mi + 8) * A_STR + k8 + quad;
                uint32_t ah[4], al[4];
                split_tf32(Am0[0], ah[0], al[0]);
                split_tf32(Am1[0], ah[1], al[1]);
                split_tf32(Am0[4], ah[2], al[2]);
                split_tf32(Am1[4], ah[3], al[3]);
                #pragma unroll
                for (int u = 0; u < 4; ++u) mma_tf32(acc[t][u], ah, bl[u]);
                #pragma unroll
                for (int u = 0; u < 4; ++u) mma_tf32(acc[t][u], al, bh[u]);
                #pragma unroll
                for (int u = 0; u < 4; ++u) mma_tf32(acc[t][u], ah, bh[u]);
            }
        }
    }

    #pragma unroll
    for (int u = 0; u < 4; ++u) {
        const int c = col0 + wn0 + 8 * u + 2 * quad;
        const float bj0 = bias[c], bj1 = bias[c + 1];
        #pragma unroll
        for (int t = 0; t < 4; ++t) {
            const int r0 = row0 + wm0 + 16 * t + qrow;
            float v00 = acc[t][u][0] + bj0;
            float v01 = acc[t][u][1] + bj1;
            float v10 = acc[t][u][2] + bj0;
            float v11 = acc[t][u][3] + bj1;
            if (RELU) {
                v00 = fmaxf(v00, 0.0f); v01 = fmaxf(v01, 0.0f);
                v10 = fmaxf(v10, 0.0f); v11 = fmaxf(v11, 0.0f);
            }
            *(float2*)(C + (size_t)r0 * N + c)       = make_float2(v00, v01);
            *(float2*)(C + (size_t)(r0 + 8) * N + c) = make_float2(v10, v11);
        }
    }
}

__global__ __launch_bounds__(256)
void rownorm_kernel()
{
    const int gtid = blockIdx.x * blockDim.x + threadIdx.x;
    const int row  = gtid >> 5;
    const int lane = gtid & 31;
    const float4* e = (const float4*)(g_E + (size_t)row * DC);
    float4 v1 = e[lane];
    float4 v2 = e[lane + 32];
    float s = v1.x * v1.x + v1.y * v1.y + v1.z * v1.z + v1.w * v1.w
            + v2.x * v2.x + v2.y * v2.y + v2.z * v2.z + v2.w * v2.w;
    #pragma unroll
    for (int off = 16; off > 0; off >>= 1)
        s += __shfl_xor_sync(0xffffffffu, s, off);
    if (lane == 0) g_rowNorm[row] = s;
}

__global__ void cnorm_kernel(const float* __restrict__ cb)
{
    const int n    = blockIdx.x;
    const int lane = threadIdx.x;
    const float4* c = (const float4*)(cb + (size_t)n * DC);
    float4 v1 = c[lane];
    float4 v2 = c[lane + 32];
    float s = v1.x * v1.x + v1.y * v1.y + v1.z * v1.z + v1.w * v1.w
            + v2.x * v2.x + v2.y * v2.y + v2.z * v2.z + v2.w * v2.w;
    #pragma unroll
    for (int off = 16; off > 0; off >>= 1)
        s += __shfl_xor_sync(0xffffffffu, s, off);
    if (lane == 0) g_cnorm[n] = s;
}

__global__ __launch_bounds__(256, 2)
void argmin_kernel(const float* __restrict__ cb, float* __restrict__ out)
{
    constexpr int BM = 128, BK = 8;
    __shared__ __align__(16) float As[2][BK][BM];
    __shared__ __align__(16) float Bs[2][BK][NC];
    __shared__ float cn[NC];

    const int tid = threadIdx.x;
    const int tx  = tid & 15;
    const int ty  = tid >> 4;
    const int row0 = blockIdx.x * BM;

    if (tid < NC) cn[tid] = g_cnorm[tid];

    const int arow = tid >> 1;
    const int acol = (tid & 1) * 4;
    const int bn   = tid >> 1;
    const int bk   = (tid & 1) * 4;

    const float* Aptr = g_E + (size_t)(row0 + arow) * DC + acol;
    const float* Bptr = cb  + (size_t)bn * DC + bk;

    float4 av = *(const float4*)Aptr;
    float4 bv = *(const float4*)Bptr;
    As[0][acol + 0][arow] = av.x;
    As[0][acol + 1][arow] = av.y;
    As[0][acol + 2][arow] = av.z;
    As[0][acol + 3][arow] = av.w;
    Bs[0][bk + 0][bn] = bv.x;
    Bs[0][bk + 1][bn] = bv.y;
    Bs[0][bk + 2][bn] = bv.z;
    Bs[0][bk + 3][bn] = bv.w;
    __syncthreads();

    float acc[8][8] = {};
    const int nk = DC / BK;
    int buf = 0;
    for (int kt = 0; kt < nk; ++kt) {
        float4 av2, bv2;
        const bool more = (kt + 1 < nk);
        if (more) {
            av2 = *(const float4*)(Aptr + (kt + 1) * BK);
            bv2 = *(const float4*)(Bptr + (kt + 1) * BK);
        }
        #pragma unroll
        for (int k = 0; k < BK; ++k) {
            float a[8], b[8];
            *(float4*)&a[0] = *(const float4*)&As[buf][k][ty * 8];
            *(float4*)&a[4] = *(const float4*)&As[buf][k][ty * 8 + 4];
            *(float4*)&b[0] = *(const float4*)&Bs[buf][k][tx * 8];
            *(float4*)&b[4] = *(const float4*)&Bs[buf][k][tx * 8 + 4];
            #pragma unroll
            for (int i = 0; i < 8; ++i)
                #pragma unroll
                for (int j = 0; j < 8; ++j)
                    acc[i][j] = fmaf(a[i], b[j], acc[i][j]);
        }
        if (more) {
            As[buf ^ 1][acol + 0][arow] = av2.x;
            As[buf ^ 1][acol + 1][arow] = av2.y;
            As[buf ^ 1][acol + 2][arow] = av2.z;
            As[buf ^ 1][acol + 3][arow] = av2.w;
            Bs[buf ^ 1][bk + 0][bn] = bv2.x;
            Bs[buf ^ 1][bk + 1][bn] = bv2.y;
            Bs[buf ^ 1][bk + 2][bn] = bv2.z;
            Bs[buf ^ 1][bk + 3][bn] = bv2.w;
            buf ^= 1;
            __syncthreads();
        }
    }

    #pragma unroll
    for (int i = 0; i < 8; ++i) {
        float mv = 3.0e38f;
        int   mi = 0;
        #pragma unroll
        for (int j = 0; j < 8; ++j) {
            float v = cn[tx * 8 + j] - 2.0f * acc[i][j];
            if (v < mv) { mv = v; mi = tx * 8 + j; }
        }
        #pragma unroll
        for (int off = 8; off >= 1; off >>= 1) {
            float ov = __shfl_xor_sync(0xffffffffu, mv, off);
            int   oi = __shfl_xor_sync(0xffffffffu, mi, off);
            if (ov < mv || (ov == mv && oi < mi)) { mv = ov; mi = oi; }
        }
        if (tx == 0) {
            const int r = row0 + ty * 8 + i;
            out[r]      = (float)mi;
            g_sqerr[r]  = g_rowNorm[r] + mv;
        }
    }
}

__global__ void reduce_loss_kernel(float* __restrict__ out)
{
    __shared__ double sm[1024];
    const int tid = threadIdx.x;
    double s = 0.0;
    for (int i = tid; i < MTOK; i += 1024) s += (double)g_sqerr[i];
    sm[tid] = s;
    __syncthreads();
    for (int off = 512; off > 0; off >>= 1) {
        if (tid < off) sm[tid] += sm[tid + off];
        __syncthreads();
    }
    if (tid == 0) {
        const float loss = (float)(sm[0] / ((double)MTOK * (double)DC));
        out[MTOK + 0] = loss;
        out[MTOK + 1] = loss;
        out[MTOK + 2] = 1.25f * loss;
    }
}

extern "C" void kernel_launch(void* const* d_in, const int* in_sizes, int n_in,
                              void* d_out, int out_size)
{
    const float* x  = (const float*)d_in[0];
    const float* W1 = (const float*)d_in[1];
    const float* b1 = (const float*)d_in[2];
    const float* W2 = (const float*)d_in[3];
    const float* b2 = (const float*)d_in[4];
    const float* cb = (const float*)d_in[5];
    float* out = (float*)d_out;

    float* H = (float*)0; float* E = (float*)0;
    cudaGetSymbolAddress((void**)&H, g_H);
    cudaGetSymbolAddress((void**)&E, g_E);

    cudaFuncSetAttribute(gemm_mma<true>,
                         cudaFuncAttributeMaxDynamicSharedMemorySize, GEMM_SMEM);
    cudaFuncSetAttribute(gemm_mma<false>,
                         cudaFuncAttributeMaxDynamicSharedMemorySize, GEMM_SMEM);

    gemm_mma<true ><<<dim3(DH / 128, MTOK / 128), 256, GEMM_SMEM>>>(x, W1, b1, H, DH, DIN);
    gemm_mma<false><<<dim3(DC / 128, MTOK / 128), 256, GEMM_SMEM>>>(H, W2, b2, E, DC, DH);
    rownorm_kernel<<<MTOK / 8, 256>>>();
    cnorm_kernel<<<NC, 32>>>(cb);
    argmin_kernel<<<MTOK / 128, 256>>>(cb, out);
    reduce_loss_kernel<<<1, 1024>>>(out);
}